// round 11
// baseline (speedup 1.0000x reference)
#include <cuda_runtime.h>
#include <cstdint>

// CTC loss forward — log2-domain forward recursion (tf.keras ctc_batch_cost
// semantics), parallelized across 4 warps: one state per thread.
//
// R8 post-mortem showed the single-warp version is instruction-ISSUE bound
// (~150 instr/step on one SMSP -> 365 cyc/step). Here block=128 threads,
// thread tid owns state s=tid (s=128 owned by thread 0 via smem), so the
// ~45-instr unified update runs on 4 SMSPs concurrently.
//
// Cross-warp s-1/s-2 neighbors: lanes 30,31 publish to parity-double-buffered
// smem, one __syncthreads per step, lanes 0,1 of warps>0 patch from smem.
// Unified update (blank/label symmetric):
//   new[s] = lae3(old[s], old[s-1], allow[s] ? old[s-2] : NEG) + e[s]
// with allow[s] = s odd && k>=1 && lab[k]!=lab[k-1], k=(s-1)/2.
//
// 2^d on the FMA pipe (exponent-split + deg-4 Taylor, d clamped >= -24);
// one MUFU __log2f per lae.

#define WARP_FULL 0xffffffffu
#define RCHUNK 8
#define NEGL  (-1e30f)
#define EPSV  (1e-7f)

// 2^d for d in [-24, 0] (caller clamps). Exponent-split + deg-4 Taylor.
__device__ __forceinline__ float p2_poly(float d) {
    float dm = d + 12582912.0f;                // 1.5*2^23 magic: rint
    float nf = dm - 12582912.0f;               // rint(d)
    float f  = d - nf;                         // [-0.5, 0.5]
    float p  = 0.0096181f;
    p = fmaf(p, f, 0.0555041f);
    p = fmaf(p, f, 0.2402265f);
    p = fmaf(p, f, 0.6931472f);
    p = fmaf(p, f, 1.0f);
    int ni = __float_as_int(dm) - 0x4B400000;  // rint(d) as int
    return __int_as_float(__float_as_int(p) + (ni << 23));
}

__global__ __launch_bounds__(128, 1)
void ctc_fwd_mw_kernel(const int* __restrict__ y_true,
                       const float* __restrict__ y_pred,
                       const int* __restrict__ input_len,
                       const int* __restrict__ label_len,
                       float* __restrict__ out,
                       int T, int C, int Lmax)
{
    const int b    = blockIdx.x;
    const int tid  = threadIdx.x;
    const int lane = tid & 31;
    const int w    = tid >> 5;

    const float* P  = y_pred + (size_t)b * T * C;
    const int*  lab = y_true + (size_t)b * Lmax;

    int L = label_len[b];
    if (L > Lmax) L = Lmax;
    int Tlen = input_len[b];
    int tEnd = Tlen < 1 ? 1 : (Tlen > T ? T : Tlen);

    const int blank = C - 1;
    const float LN2 = 0.6931471805599453f;

    const int  s    = tid;                       // owned state
    const int  k    = (s - 1) >> 1;              // label index for odd s
    const bool odd  = (s & 1) != 0;
    const int  cls  = odd ? lab[k] : blank;      // emission class (k<=63)
    const bool allow = odd && (k >= 1) && (lab[k] != lab[k - 1]);

    __shared__ float pub[2][4][2];               // [parity][warp][lane30,lane31]
    __shared__ float sA[129];

    // ---- t = 0 init (log2 domain) ----
    float A = NEGL, A128 = NEGL;                 // A128 live only on thread 0
    {
        float e0 = __log2f(__ldg(P + cls) + EPSV);
        if (s == 0)               A = e0;
        else if (s == 1 && L > 0) A = e0;
    }

    // ---- prefetch raw probs for t = 1..RCHUNK (1 float per thread) ----
    float pr[RCHUNK];
    #pragma unroll
    for (int j = 0; j < RCHUNK; j++) {
        int t = 1 + j;
        pr[j] = __ldg(P + (size_t)(t < T ? t : T - 1) * C + cls);
    }

    int par = 0;
    for (int tb = 1; tb < tEnd; tb += RCHUNK) {
        // issue next chunk's loads
        float nx[RCHUNK];
        #pragma unroll
        for (int j = 0; j < RCHUNK; j++) {
            int t = tb + RCHUNK + j;
            nx[j] = __ldg(P + (size_t)(t < T ? t : T - 1) * C + cls);
        }
        // emissions for this chunk (off the serial chain)
        float e[RCHUNK];
        #pragma unroll
        for (int j = 0; j < RCHUNK; j++) e[j] = __log2f(pr[j] + EPSV);

        #pragma unroll
        for (int j = 0; j < RCHUNK; j++) {
            int t = tb + j;

            // publish boundary states (old values) for the next warp
            if (lane >= 30) pub[par][w][lane - 30] = A;
            __syncthreads();

            float u1 = __shfl_up_sync(WARP_FULL, A, 1);   // old[s-1]
            float u2 = __shfl_up_sync(WARP_FULL, A, 2);   // old[s-2]
            if (w > 0) {
                if (lane == 0)      { u1 = pub[par][w-1][1]; u2 = pub[par][w-1][0]; }
                else if (lane == 1) {                        u2 = pub[par][w-1][1]; }
            }
            float bv = (s >= 1) ? u1 : NEGL;
            float cv = allow    ? u2 : NEGL;

            float m   = fmaxf(fmaxf(A, bv), cv);
            float sum = p2_poly(fmaxf(A  - m, -24.f))
                      + p2_poly(fmaxf(bv - m, -24.f))
                      + p2_poly(fmaxf(cv - m, -24.f));
            float nA  = m + __log2f(sum) + e[j];

            // thread 0 also advances state 128 (blank): lae2(old128, old127)
            float nA128 = A128;
            if (tid == 0) {
                float o127 = pub[par][3][1];
                float m2   = fmaxf(A128, o127);
                float s2   = p2_poly(fmaxf(A128 - m2, -24.f))
                           + p2_poly(fmaxf(o127 - m2, -24.f));
                nA128 = m2 + __log2f(s2) + e[j];          // e[j] = blank for tid 0
            }

            if (t < tEnd) { A = nA; A128 = nA128; }
            par ^= 1;
        }

        #pragma unroll
        for (int j = 0; j < RCHUNK; j++) pr[j] = nx[j];
    }

    // ---- final readout: ll = ln2 * logaddexp2(a[2L], a[2L-1]) ----
    sA[s] = A;
    if (tid == 0) sA[128] = A128;
    __syncthreads();

    if (tid == 0) {
        float a_last = sA[2 * L];
        float a_prev = (L > 0) ? sA[2 * L - 1] : NEGL;
        float m = fmaxf(a_last, a_prev);
        float d = fmaxf(fminf(a_last, a_prev) - m, -24.f);
        float ll2 = m + __log2f(1.0f + p2_poly(d));
        out[b] = -(ll2 * LN2);
    }
}

extern "C" void kernel_launch(void* const* d_in, const int* in_sizes, int n_in,
                              void* d_out, int out_size)
{
    const int*   y_true    = (const int*)  d_in[0];
    const float* y_pred    = (const float*)d_in[1];
    const int*   input_len = (const int*)  d_in[2];
    const int*   label_len = (const int*)  d_in[3];
    float* out = (float*)d_out;

    int B = out_size;                    // out is [B,1]
    int Lmax = in_sizes[0] / B;          // 64
    int C = 256;
    int T = in_sizes[1] / (B * C);       // 1024

    ctc_fwd_mw_kernel<<<B, 128>>>(y_true, y_pred, input_len, label_len, out, T, C, Lmax);
}